// round 16
// baseline (speedup 1.0000x reference)
#include <cuda_runtime.h>
#include <math_constants.h>
#include <stdint.h>

// ===========================================================================
// MAM dense: C[m,n] = max_k(A[m,k]*W[n,k]) + min_k(A[m,k]*W[n,k]) + bias[n]
// plus argmax/argmin index planes (as float).
//
// Pipeline (fast path K=N=1024, M%32==0, M<=8192):
//   P0 : transpose A -> At[k][m], W -> Wt[k][n] (one merged launch);
//   P1 : per-row top-56 |x| candidates (fp bisection threshold), ascending k,
//        padded with the last real candidate (one merged launch, also zeroes
//        the worklist counter).
//   P3 : candidate evaluation (R12 structure), 32x32 outputs/block, 1024
//        threads, no tiles:
//        loop1: warp=m, lanes=n, per-candidate coalesced LDG of Wt row;
//        loop2: warp=n, lanes=m, per-candidate coalesced LDG of At row;
//        fixed-trip unrolled loops, role transpose via smem exchange.
//        Soundness check vs theta_a*theta_w; failures -> global worklist.
//   P4 : cleanup — one warp per failing (m,n), exact full-K scan.
// Exactness: ascending-k candidate order + strict compares; all merges break
// value ties by min index (jnp first-occurrence semantics). rel_err == 0.
// ===========================================================================

#define T_CAND 56
#define MAXM 8192
#define NW 1024

__device__ float g_At[(size_t)MAXM * 1024];   // [K][M]
__device__ float g_Wt[(size_t)NW * 1024];     // [K][N]
__device__ int2  g_ca[MAXM * T_CAND];         // (k, float_bits) per A row
__device__ int2  g_cw[NW * T_CAND];           // (k, float_bits) per W row
__device__ float g_th_a[MAXM];
__device__ float g_th_w[NW];
__device__ int      g_cnt;
__device__ unsigned g_work[(size_t)MAXM * NW];

// ---------------------------------------------------------------------------
// merged transpose: A[M][1024]->At[1024][M] and W[1024][1024]->Wt[1024][1024]
// grid: x = M/32 + 32 (row-tiles, A then W), y = 32 (col-tiles)
// ---------------------------------------------------------------------------
__global__ __launch_bounds__(256)
void transpose2_kernel(const float* __restrict__ A, const float* __restrict__ W,
                       float* __restrict__ At, float* __restrict__ Wt, int M) {
    __shared__ float t[32][33];
    const int MA32 = M >> 5;
    const float* X;
    float* Xt;
    int R, r0;
    if ((int)blockIdx.x < MA32) {
        X = A; Xt = At; R = M; r0 = blockIdx.x * 32;
    } else {
        X = W; Xt = Wt; R = 1024; r0 = (blockIdx.x - MA32) * 32;
    }
    const int c0 = blockIdx.y * 32;
    const int x = threadIdx.x, y = threadIdx.y;   // 32 x 8
#pragma unroll
    for (int i = 0; i < 32; i += 8)
        t[y + i][x] = X[(size_t)(r0 + y + i) * 1024 + c0 + x];
    __syncthreads();
#pragma unroll
    for (int i = 0; i < 32; i += 8)
        Xt[(size_t)(c0 + y + i) * R + r0 + x] = t[x][y + i];
}

// ---------------------------------------------------------------------------
// P1: per-row top-|x| candidates, one warp per row, K=1024 fixed.
// Merged: blocks [0, M/8) handle A rows, [M/8, M/8+N/8) handle W rows.
// Also zeroes the worklist counter (consumed only by the later P3 kernel).
// ---------------------------------------------------------------------------
__global__ __launch_bounds__(256)
void topk_kernel(const float* __restrict__ A, const float* __restrict__ W,
                 int rowsA, int rowsW) {
    if (blockIdx.x == 0 && threadIdx.x == 0) g_cnt = 0;

    const int warp = threadIdx.x >> 5;
    const int lane = threadIdx.x & 31;
    int row = blockIdx.x * 8 + warp;
    const unsigned FULL = 0xffffffffu;

    const float* X;
    int2*  lst;
    float* thL;
    if (row < rowsA) {
        X = A; lst = g_ca; thL = g_th_a;
    } else {
        row -= rowsA;
        if (row >= rowsW) return;
        X = W; lst = g_cw; thL = g_th_w;
    }

    float s[32];
    const float* Xr = X + (size_t)row * 1024;
#pragma unroll
    for (int j = 0; j < 32; j++) s[j] = Xr[j * 32 + lane];

    float rmax = 0.f;
#pragma unroll
    for (int j = 0; j < 32; j++) rmax = fmaxf(rmax, fabsf(s[j]));
    for (int o = 16; o; o >>= 1) rmax = fmaxf(rmax, __shfl_xor_sync(FULL, rmax, o));

    // bisection: smallest t with count(|x| >= t) <= T_CAND (hi keeps invariant)
    float lo = 0.f, hi = rmax;
    for (int it = 0; it < 16; it++) {
        float mid = 0.5f * (lo + hi);
        int c = 0;
#pragma unroll
        for (int j = 0; j < 32; j++) c += (fabsf(s[j]) >= mid);
        for (int o = 16; o; o >>= 1) c += __shfl_xor_sync(FULL, c, o);
        if (c > T_CAND) lo = mid; else hi = mid;
    }
    const float theta = hi;

    // ascending-k compaction
    int slot = 0;
    int   bestpos = -1, bestidx = 0;
    float bestval = 0.f;
    int2* my = lst + (size_t)row * T_CAND;
#pragma unroll
    for (int j = 0; j < 32; j++) {
        bool pr = (fabsf(s[j]) >= theta);
        unsigned msk = __ballot_sync(FULL, pr);
        if (pr) {
            int pos = slot + __popc(msk & ((1u << lane) - 1u));
            my[pos] = make_int2(j * 32 + lane, __float_as_int(s[j]));
            bestpos = pos; bestidx = j * 32 + lane; bestval = s[j];
        }
        slot += __popc(msk);
    }
    for (int o = 16; o; o >>= 1) {
        int   opos = __shfl_xor_sync(FULL, bestpos, o);
        int   oidx = __shfl_xor_sync(FULL, bestidx, o);
        float oval = __shfl_xor_sync(FULL, bestval, o);
        if (opos > bestpos) { bestpos = opos; bestidx = oidx; bestval = oval; }
    }
    // pad with last real candidate (exact self-tie, ascending preserved)
    for (int p = slot + lane; p < T_CAND; p += 32)
        my[p] = make_int2(bestidx, __float_as_int(bestval));
    if (lane == 0) thL[row] = theta;
}

// ---------------------------------------------------------------------------
// P3: candidate evaluation (R12 structure), per-candidate coalesced LDG.
// ---------------------------------------------------------------------------
#define UPDX(P, KK, VX, IX, VN, IN)                                          \
    { bool _g = (P) > (VX); (VX) = _g ? (P) : (VX);                          \
      if (WIDX) (IX) = _g ? (KK) : (IX);                                     \
      bool _l = (P) < (VN); (VN) = _l ? (P) : (VN);                          \
      if (WIDX) (IN) = _l ? (KK) : (IN); }

template <int WIDX>
__global__ __launch_bounds__(1024, 2)
void mam_cand_kernel(const float* __restrict__ At, const float* __restrict__ Wt,
                     const float* __restrict__ bias, float* __restrict__ out,
                     int M) {
    __shared__ int2  sCand[2 * 32 * T_CAND];   // [Ca | Cw], 28.7KB
    __shared__ float sThA[32], sThW[32];

    const int tid  = threadIdx.x;
    const int wid  = tid >> 5;
    const int lane = tid & 31;
    const int m0 = blockIdx.y * 32;
    const int n0 = blockIdx.x * 32;
    const unsigned FULL = 0xffffffffu;

    int2* sCa = sCand;
    int2* sCw = sCand + 32 * T_CAND;

    for (int i = tid; i < 32 * T_CAND; i += 1024) {
        sCa[i] = g_ca[(size_t)m0 * T_CAND + i];
        sCw[i] = g_cw[(size_t)n0 * T_CAND + i];
    }
    if (tid < 32) {
        sThA[tid] = g_th_a[m0 + tid];
        sThW[tid] = g_th_w[n0 + tid];
    }
    __syncthreads();

    float vmax = -CUDART_INF_F, vmin = CUDART_INF_F;
    int   imax = 0, imin = 0;          // loop1 acc: output (m0+wid, n0+lane)
    float vmax2 = -CUDART_INF_F, vmin2 = CUDART_INF_F;
    int   imax2 = 0, imin2 = 0;        // loop2 acc: output (m0+lane, n0+wid)

    // ---- loop1: warp = m (wid), lanes = n. Candidates of A row m. ----
    {
        const int2* ca = sCa + wid * T_CAND;
        const float* wcol = Wt + n0 + lane;
#pragma unroll 4
        for (int j = 0; j < T_CAND; j += 2) {
            int4 q = *reinterpret_cast<const int4*>(ca + j);
            float w0 = __ldg(wcol + (size_t)q.x * NW);
            float w1 = __ldg(wcol + (size_t)q.z * NW);
            float p0 = __int_as_float(q.y) * w0;
            UPDX(p0, q.x, vmax, imax, vmin, imin);
            float p1 = __int_as_float(q.w) * w1;
            UPDX(p1, q.z, vmax, imax, vmin, imin);
        }
    }

    // ---- loop2: warp = n (wid), lanes = m. Candidates of W row n. ----
    {
        const int2* cw = sCw + wid * T_CAND;
        const float* acol = At + m0 + lane;
#pragma unroll 4
        for (int j = 0; j < T_CAND; j += 2) {
            int4 q = *reinterpret_cast<const int4*>(cw + j);
            float a0 = __ldg(acol + (size_t)q.x * M);
            float a1 = __ldg(acol + (size_t)q.z * M);
            float p0 = a0 * __int_as_float(q.y);
            UPDX(p0, q.x, vmax2, imax2, vmin2, imin2);
            float p1 = a1 * __int_as_float(q.w);
            UPDX(p1, q.z, vmax2, imax2, vmin2, imin2);
        }
    }

    // ---- exchange loop2 results to loop1's thread mapping (overlay sCand) --
    __syncthreads();
    int4* sX = (int4*)sCand;   // 32*33*16 = 16.9KB < 28.7KB
    sX[lane * 33 + wid] = make_int4(__float_as_int(vmax2), imax2,
                                    __float_as_int(vmin2), imin2);
    __syncthreads();
    {
        int4 e = sX[wid * 33 + lane];
        float xv = __int_as_float(e.x), nv = __int_as_float(e.z);
        if (WIDX) {
            if (xv > vmax || (xv == vmax && e.y < imax)) { vmax = xv; imax = e.y; }
            if (nv < vmin || (nv == vmin && e.w < imin)) { vmin = nv; imin = e.w; }
        } else {
            vmax = fmaxf(vmax, xv);
            vmin = fminf(vmin, nv);
        }
    }

    const int mg = m0 + wid, ng = n0 + lane;

    // ---- soundness check -> worklist (warp-aggregated) ----
    float bnd = sThA[wid] * sThW[lane] * 1.000001f;
    bool bad = !(vmax >= bnd && vmin <= -bnd);
    unsigned msk = __ballot_sync(FULL, bad);
    if (msk) {
        int base = 0;
        int leader = __ffs(msk) - 1;
        if (lane == leader) base = atomicAdd(&g_cnt, __popc(msk));
        base = __shfl_sync(FULL, base, leader);
        if (bad) {
            int pos = base + __popc(msk & ((1u << lane) - 1u));
            g_work[pos] = ((unsigned)mg << 10) | (unsigned)ng;
        }
    }

    const size_t MN = (size_t)M * NW;
    const size_t o  = (size_t)mg * NW + ng;
    out[o] = vmax + vmin + bias[ng];
    if (WIDX) {
        out[MN + o]     = (float)imax;
        out[2 * MN + o] = (float)imin;
    }
}

// ---------------------------------------------------------------------------
// P4: exact cleanup — one warp per failing (m,n).
// ---------------------------------------------------------------------------
__global__ __launch_bounds__(256)
void cleanup_kernel(const float* __restrict__ A, const float* __restrict__ W,
                    const float* __restrict__ bias, float* __restrict__ out,
                    int M, int widx) {
    const unsigned FULL = 0xffffffffu;
    const int lane = threadIdx.x & 31;
    const int gwarp = (blockIdx.x * blockDim.x + threadIdx.x) >> 5;
    const int nwarps = (gridDim.x * blockDim.x) >> 5;
    const int cnt = g_cnt;
    const size_t MN = (size_t)M * NW;

    for (int i = gwarp; i < cnt; i += nwarps) {
        unsigned e = g_work[i];
        int m = (int)(e >> 10), n = (int)(e & 1023u);
        const float4* Ar = reinterpret_cast<const float4*>(A + (size_t)m * 1024) + lane * 8;
        const float4* Wr = reinterpret_cast<const float4*>(W + (size_t)n * 1024) + lane * 8;

        float vmax = -CUDART_INF_F, vmin = CUDART_INF_F;
        int   imax = 0, imin = 0;
#pragma unroll
        for (int j = 0; j < 8; j++) {
            float4 a = Ar[j];
            float4 w = Wr[j];
            int k0 = lane * 32 + j * 4;
            float pv[4] = {a.x * w.x, a.y * w.y, a.z * w.z, a.w * w.w};
#pragma unroll
            for (int q = 0; q < 4; q++) {
                bool g = pv[q] > vmax; vmax = g ? pv[q] : vmax; imax = g ? (k0 + q) : imax;
                bool l = pv[q] < vmin; vmin = l ? pv[q] : vmin; imin = l ? (k0 + q) : imin;
            }
        }
        for (int o = 16; o; o >>= 1) {
            float ov = __shfl_xor_sync(FULL, vmax, o);
            int   oi = __shfl_xor_sync(FULL, imax, o);
            if (ov > vmax || (ov == vmax && oi < imax)) { vmax = ov; imax = oi; }
            float uv = __shfl_xor_sync(FULL, vmin, o);
            int   ui = __shfl_xor_sync(FULL, imin, o);
            if (uv < vmin || (uv == vmin && ui < imin)) { vmin = uv; imin = ui; }
        }
        if (lane == 0) {
            size_t o = (size_t)m * NW + n;
            out[o] = vmax + vmin + bias[n];
            if (widx) {
                out[MN + o]     = (float)imax;
                out[2 * MN + o] = (float)imin;
            }
        }
    }
}

// ---------------------------------------------------------------------------
// fallback exhaustive kernel (unexpected shapes only)
// ---------------------------------------------------------------------------
#define BM 128
#define BN 64
#define BK 16
#define TM 8
#define TN 4
#define THREADS 256

template <bool WIDX>
__global__ __launch_bounds__(THREADS)
void mam_kernel(const float* __restrict__ A, const float* __restrict__ W,
                const float* __restrict__ bias, float* __restrict__ out,
                int M, int N, int K) {
    __shared__ float As[BK][BM + 4];
    __shared__ float Ws[BK][BN + 4];
    const int tid = threadIdx.x;
    const int tx = tid & 15, ty = tid >> 4;
    const int m0 = blockIdx.y * BM, n0 = blockIdx.x * BN;
    float vmax[TM][TN], vmin[TM][TN];
    int   imax[TM][TN], imin[TM][TN];
#pragma unroll
    for (int i = 0; i < TM; i++)
#pragma unroll
        for (int j = 0; j < TN; j++) {
            vmax[i][j] = -CUDART_INF_F; vmin[i][j] = CUDART_INF_F;
            if (WIDX) { imax[i][j] = 0; imin[i][j] = 0; }
        }
    const float* Ablk = A + (size_t)m0 * K;
    const float* Wblk = W + (size_t)n0 * K;
    for (int k0 = 0; k0 < K; k0 += BK) {
#pragma unroll
        for (int r = 0; r < (BM * BK) / THREADS; r++) {
            int idx = tid + r * THREADS;
            As[idx & 15][idx >> 4] = Ablk[(size_t)(idx >> 4) * K + (k0 + (idx & 15))];
        }
#pragma unroll
        for (int r = 0; r < (BN * BK) / THREADS; r++) {
            int idx = tid + r * THREADS;
            Ws[idx & 15][idx >> 4] = Wblk[(size_t)(idx >> 4) * K + (k0 + (idx & 15))];
        }
        __syncthreads();
#pragma unroll 4
        for (int kk = 0; kk < BK; kk++) {
            float a[TM], w[TN];
#pragma unroll
            for (int i = 0; i < TM; i++) a[i] = As[kk][ty * TM + i];
#pragma unroll
            for (int j = 0; j < TN; j++) w[j] = Ws[kk][tx * TN + j];
            const int kg = k0 + kk;
#pragma unroll
            for (int i = 0; i < TM; i++)
#pragma unroll
                for (int j = 0; j < TN; j++) {
                    float p = a[i] * w[j];
                    bool gm = p > vmax[i][j];
                    vmax[i][j] = gm ? p : vmax[i][j];
                    if (WIDX) imax[i][j] = gm ? kg : imax[i][j];
                    bool gn = p < vmin[i][j];
                    vmin[i][j] = gn ? p : vmin[i][j];
                    if (WIDX) imin[i][j] = gn ? kg : imin[i][j];
                }
        }
        __syncthreads();
    }
    const size_t MN = (size_t)M * N;
#pragma unroll
    for (int i = 0; i < TM; i++) {
        int m = m0 + ty * TM + i;
        size_t row = (size_t)m * N + n0 + tx * TN;
#pragma unroll
        for (int j = 0; j < TN; j++) {
            out[row + j] = vmax[i][j] + vmin[i][j] + bias[n0 + tx * TN + j];
            if (WIDX) {
                out[MN + row + j] = (float)imax[i][j];
                out[2 * MN + row + j] = (float)imin[i][j];
            }
        }
    }
}

// ---------------------------------------------------------------------------
extern "C" void kernel_launch(void* const* d_in, const int* in_sizes, int n_in,
                              void* d_out, int out_size) {
    const float* x = (const float*)d_in[0];
    const float* w = (const float*)d_in[1];
    const float* b = (const float*)d_in[2];
    float* out = (float*)d_out;

    const int N = in_sizes[2];
    const int K = in_sizes[1] / N;
    const int M = in_sizes[0] / K;
    const long long MN = (long long)M * (long long)N;
    const int widx = ((long long)out_size >= 3 * MN) ? 1 : 0;

    if (K == 1024 && N == 1024 && M <= MAXM && (M % 32) == 0) {
        float* At; cudaGetSymbolAddress((void**)&At, g_At);
        float* Wt; cudaGetSymbolAddress((void**)&Wt, g_Wt);

        {   // merged transpose: A row-tiles then W row-tiles
            dim3 blk(32, 8);
            dim3 g(M / 32 + 1024 / 32, 32);
            transpose2_kernel<<<g, blk>>>(x, w, At, Wt, M);
        }
        // merged topk (also zeroes worklist counter)
        topk_kernel<<<(M + N) / 8, 256>>>(x, w, M, N);

        dim3 grid(N / 32, M / 32);
        if (widx) mam_cand_kernel<1><<<grid, 1024>>>(At, Wt, b, out, M);
        else      mam_cand_kernel<0><<<grid, 1024>>>(At, Wt, b, out, M);

        cleanup_kernel<<<1184, 256>>>(x, w, b, out, M, widx);
    } else {
        dim3 grid(N / BN, M / BM);
        if (widx) mam_kernel<true><<<grid, THREADS>>>(x, w, b, out, M, N, K);
        else      mam_kernel<false><<<grid, THREADS>>>(x, w, b, out, M, N, K);
    }
}

// round 17
// speedup vs baseline: 1.3139x; 1.3139x over previous
#include <cuda_runtime.h>
#include <math_constants.h>
#include <stdint.h>

// ===========================================================================
// MAM dense: C[m,n] = max_k(A[m,k]*W[n,k]) + min_k(A[m,k]*W[n,k]) + bias[n]
// plus argmax/argmin index planes (as float).
//
// Pipeline (fast path K=N=1024, M%32==0, M<=8192):
//   P0 : transpose A -> At[k][m], W -> Wt[k][n] (one merged launch)
//   P1 : per-row top-64 |x| candidates (fp bisection threshold), ascending k,
//        padded with the last real candidate (one merged launch; also zeroes
//        the worklist counter).
//   P3 : candidate evaluation (R12 structure), 32x32 outputs/block, 1024
//        threads, no tiles:
//        loop1: warp=m, lanes=n, per-candidate coalesced LDG of Wt row;
//        loop2: warp=n, lanes=m, per-candidate coalesced LDG of At row;
//        fixed 64-trip unrolled loops, role transpose via smem exchange.
//        Soundness check vs theta_a*theta_w; failures -> global worklist.
//   P4 : cleanup — one warp per failing (m,n), exact full-K scan.
// Exactness: ascending-k candidate order + strict compares; all merges break
// value ties by min index (jnp first-occurrence semantics). rel_err == 0.
//
// NOTE (R16 post-mortem): T_CAND is calibrated at 64 — T=56 exploded the
// soundness-failure rate (cleanup 300us). Do not reduce T.
// ===========================================================================

#define T_CAND 64
#define MAXM 8192
#define NW 1024

__device__ float g_At[(size_t)MAXM * 1024];   // [K][M]
__device__ float g_Wt[(size_t)NW * 1024];     // [K][N]
__device__ int2  g_ca[MAXM * T_CAND];         // (k, float_bits) per A row
__device__ int2  g_cw[NW * T_CAND];           // (k, float_bits) per W row
__device__ float g_th_a[MAXM];
__device__ float g_th_w[NW];
__device__ int      g_cnt;
__device__ unsigned g_work[(size_t)MAXM * NW];

// ---------------------------------------------------------------------------
// merged transpose: A[M][1024]->At[1024][M] and W[1024][1024]->Wt[1024][1024]
// grid: x = M/32 + 32 (row-tiles, A then W), y = 32 (col-tiles)
// ---------------------------------------------------------------------------
__global__ __launch_bounds__(256)
void transpose2_kernel(const float* __restrict__ A, const float* __restrict__ W,
                       float* __restrict__ At, float* __restrict__ Wt, int M) {
    __shared__ float t[32][33];
    const int MA32 = M >> 5;
    const float* X;
    float* Xt;
    int R, r0;
    if ((int)blockIdx.x < MA32) {
        X = A; Xt = At; R = M; r0 = blockIdx.x * 32;
    } else {
        X = W; Xt = Wt; R = 1024; r0 = (blockIdx.x - MA32) * 32;
    }
    const int c0 = blockIdx.y * 32;
    const int x = threadIdx.x, y = threadIdx.y;   // 32 x 8
#pragma unroll
    for (int i = 0; i < 32; i += 8)
        t[y + i][x] = X[(size_t)(r0 + y + i) * 1024 + c0 + x];
    __syncthreads();
#pragma unroll
    for (int i = 0; i < 32; i += 8)
        Xt[(size_t)(c0 + y + i) * R + r0 + x] = t[x][y + i];
}

// ---------------------------------------------------------------------------
// P1: per-row top-|x| candidates, one warp per row, K=1024 fixed.
// Merged: blocks [0, M/8) handle A rows, [M/8, M/8+N/8) handle W rows.
// Also zeroes the worklist counter (consumed only by the later P3 kernel).
// ---------------------------------------------------------------------------
__global__ __launch_bounds__(256)
void topk_kernel(const float* __restrict__ A, const float* __restrict__ W,
                 int rowsA, int rowsW) {
    if (blockIdx.x == 0 && threadIdx.x == 0) g_cnt = 0;

    const int warp = threadIdx.x >> 5;
    const int lane = threadIdx.x & 31;
    int row = blockIdx.x * 8 + warp;
    const unsigned FULL = 0xffffffffu;

    const float* X;
    int2*  lst;
    float* thL;
    if (row < rowsA) {
        X = A; lst = g_ca; thL = g_th_a;
    } else {
        row -= rowsA;
        if (row >= rowsW) return;
        X = W; lst = g_cw; thL = g_th_w;
    }

    float s[32];
    const float* Xr = X + (size_t)row * 1024;
#pragma unroll
    for (int j = 0; j < 32; j++) s[j] = Xr[j * 32 + lane];

    float rmax = 0.f;
#pragma unroll
    for (int j = 0; j < 32; j++) rmax = fmaxf(rmax, fabsf(s[j]));
    for (int o = 16; o; o >>= 1) rmax = fmaxf(rmax, __shfl_xor_sync(FULL, rmax, o));

    // bisection: smallest t with count(|x| >= t) <= T_CAND (hi keeps invariant)
    float lo = 0.f, hi = rmax;
    for (int it = 0; it < 16; it++) {
        float mid = 0.5f * (lo + hi);
        int c = 0;
#pragma unroll
        for (int j = 0; j < 32; j++) c += (fabsf(s[j]) >= mid);
        for (int o = 16; o; o >>= 1) c += __shfl_xor_sync(FULL, c, o);
        if (c > T_CAND) lo = mid; else hi = mid;
    }
    const float theta = hi;

    // ascending-k compaction
    int slot = 0;
    int   bestpos = -1, bestidx = 0;
    float bestval = 0.f;
    int2* my = lst + (size_t)row * T_CAND;
#pragma unroll
    for (int j = 0; j < 32; j++) {
        bool pr = (fabsf(s[j]) >= theta);
        unsigned msk = __ballot_sync(FULL, pr);
        if (pr) {
            int pos = slot + __popc(msk & ((1u << lane) - 1u));
            my[pos] = make_int2(j * 32 + lane, __float_as_int(s[j]));
            bestpos = pos; bestidx = j * 32 + lane; bestval = s[j];
        }
        slot += __popc(msk);
    }
    for (int o = 16; o; o >>= 1) {
        int   opos = __shfl_xor_sync(FULL, bestpos, o);
        int   oidx = __shfl_xor_sync(FULL, bestidx, o);
        float oval = __shfl_xor_sync(FULL, bestval, o);
        if (opos > bestpos) { bestpos = opos; bestidx = oidx; bestval = oval; }
    }
    // pad with last real candidate (exact self-tie, ascending preserved)
    for (int p = slot + lane; p < T_CAND; p += 32)
        my[p] = make_int2(bestidx, __float_as_int(bestval));
    if (lane == 0) thL[row] = theta;
}

// ---------------------------------------------------------------------------
// P3: candidate evaluation (R12 structure), per-candidate coalesced LDG.
// ---------------------------------------------------------------------------
#define UPDX(P, KK, VX, IX, VN, IN)                                          \
    { bool _g = (P) > (VX); (VX) = _g ? (P) : (VX);                          \
      if (WIDX) (IX) = _g ? (KK) : (IX);                                     \
      bool _l = (P) < (VN); (VN) = _l ? (P) : (VN);                          \
      if (WIDX) (IN) = _l ? (KK) : (IN); }

template <int WIDX>
__global__ __launch_bounds__(1024, 2)
void mam_cand_kernel(const float* __restrict__ At, const float* __restrict__ Wt,
                     const float* __restrict__ bias, float* __restrict__ out,
                     int M) {
    __shared__ int2  sCand[2 * 32 * T_CAND];   // [Ca | Cw], 32KB
    __shared__ float sThA[32], sThW[32];

    const int tid  = threadIdx.x;
    const int wid  = tid >> 5;
    const int lane = tid & 31;
    const int m0 = blockIdx.y * 32;
    const int n0 = blockIdx.x * 32;
    const unsigned FULL = 0xffffffffu;

    int2* sCa = sCand;
    int2* sCw = sCand + 32 * T_CAND;

    for (int i = tid; i < 32 * T_CAND; i += 1024) {
        sCa[i] = g_ca[(size_t)m0 * T_CAND + i];
        sCw[i] = g_cw[(size_t)n0 * T_CAND + i];
    }
    if (tid < 32) {
        sThA[tid] = g_th_a[m0 + tid];
        sThW[tid] = g_th_w[n0 + tid];
    }
    __syncthreads();

    float vmax = -CUDART_INF_F, vmin = CUDART_INF_F;
    int   imax = 0, imin = 0;          // loop1 acc: output (m0+wid, n0+lane)
    float vmax2 = -CUDART_INF_F, vmin2 = CUDART_INF_F;
    int   imax2 = 0, imin2 = 0;        // loop2 acc: output (m0+lane, n0+wid)

    // ---- loop1: warp = m (wid), lanes = n. Candidates of A row m. ----
    {
        const int2* ca = sCa + wid * T_CAND;
        const float* wcol = Wt + n0 + lane;
#pragma unroll 4
        for (int j = 0; j < T_CAND; j += 2) {
            int4 q = *reinterpret_cast<const int4*>(ca + j);
            float w0 = __ldg(wcol + (size_t)q.x * NW);
            float w1 = __ldg(wcol + (size_t)q.z * NW);
            float p0 = __int_as_float(q.y) * w0;
            UPDX(p0, q.x, vmax, imax, vmin, imin);
            float p1 = __int_as_float(q.w) * w1;
            UPDX(p1, q.z, vmax, imax, vmin, imin);
        }
    }

    // ---- loop2: warp = n (wid), lanes = m. Candidates of W row n. ----
    {
        const int2* cw = sCw + wid * T_CAND;
        const float* acol = At + m0 + lane;
#pragma unroll 4
        for (int j = 0; j < T_CAND; j += 2) {
            int4 q = *reinterpret_cast<const int4*>(cw + j);
            float a0 = __ldg(acol + (size_t)q.x * M);
            float a1 = __ldg(acol + (size_t)q.z * M);
            float p0 = a0 * __int_as_float(q.y);
            UPDX(p0, q.x, vmax2, imax2, vmin2, imin2);
            float p1 = a1 * __int_as_float(q.w);
            UPDX(p1, q.z, vmax2, imax2, vmin2, imin2);
        }
    }

    // ---- exchange loop2 results to loop1's thread mapping (overlay sCand) --
    __syncthreads();
    int4* sX = (int4*)sCand;   // 32*33*16 = 16.9KB < 32KB
    sX[lane * 33 + wid] = make_int4(__float_as_int(vmax2), imax2,
                                    __float_as_int(vmin2), imin2);
    __syncthreads();
    {
        int4 e = sX[wid * 33 + lane];
        float xv = __int_as_float(e.x), nv = __int_as_float(e.z);
        if (WIDX) {
            if (xv > vmax || (xv == vmax && e.y < imax)) { vmax = xv; imax = e.y; }
            if (nv < vmin || (nv == vmin && e.w < imin)) { vmin = nv; imin = e.w; }
        } else {
            vmax = fmaxf(vmax, xv);
            vmin = fminf(vmin, nv);
        }
    }

    const int mg = m0 + wid, ng = n0 + lane;

    // ---- soundness check -> worklist (warp-aggregated) ----
    float bnd = sThA[wid] * sThW[lane] * 1.000001f;
    bool bad = !(vmax >= bnd && vmin <= -bnd);
    unsigned msk = __ballot_sync(FULL, bad);
    if (msk) {
        int base = 0;
        int leader = __ffs(msk) - 1;
        if (lane == leader) base = atomicAdd(&g_cnt, __popc(msk));
        base = __shfl_sync(FULL, base, leader);
        if (bad) {
            int pos = base + __popc(msk & ((1u << lane) - 1u));
            g_work[pos] = ((unsigned)mg << 10) | (unsigned)ng;
        }
    }

    const size_t MN = (size_t)M * NW;
    const size_t o  = (size_t)mg * NW + ng;
    out[o] = vmax + vmin + bias[ng];
    if (WIDX) {
        out[MN + o]     = (float)imax;
        out[2 * MN + o] = (float)imin;
    }
}

// ---------------------------------------------------------------------------
// P4: exact cleanup — one warp per failing (m,n).
// ---------------------------------------------------------------------------
__global__ __launch_bounds__(256)
void cleanup_kernel(const float* __restrict__ A, const float* __restrict__ W,
                    const float* __restrict__ bias, float* __restrict__ out,
                    int M, int widx) {
    const unsigned FULL = 0xffffffffu;
    const int lane = threadIdx.x & 31;
    const int gwarp = (blockIdx.x * blockDim.x + threadIdx.x) >> 5;
    const int nwarps = (gridDim.x * blockDim.x) >> 5;
    const int cnt = g_cnt;
    const size_t MN = (size_t)M * NW;

    for (int i = gwarp; i < cnt; i += nwarps) {
        unsigned e = g_work[i];
        int m = (int)(e >> 10), n = (int)(e & 1023u);
        const float4* Ar = reinterpret_cast<const float4*>(A + (size_t)m * 1024) + lane * 8;
        const float4* Wr = reinterpret_cast<const float4*>(W + (size_t)n * 1024) + lane * 8;

        float vmax = -CUDART_INF_F, vmin = CUDART_INF_F;
        int   imax = 0, imin = 0;
#pragma unroll
        for (int j = 0; j < 8; j++) {
            float4 a = Ar[j];
            float4 w = Wr[j];
            int k0 = lane * 32 + j * 4;
            float pv[4] = {a.x * w.x, a.y * w.y, a.z * w.z, a.w * w.w};
#pragma unroll
            for (int q = 0; q < 4; q++) {
                bool g = pv[q] > vmax; vmax = g ? pv[q] : vmax; imax = g ? (k0 + q) : imax;
                bool l = pv[q] < vmin; vmin = l ? pv[q] : vmin; imin = l ? (k0 + q) : imin;
            }
        }
        for (int o = 16; o; o >>= 1) {
            float ov = __shfl_xor_sync(FULL, vmax, o);
            int   oi = __shfl_xor_sync(FULL, imax, o);
            if (ov > vmax || (ov == vmax && oi < imax)) { vmax = ov; imax = oi; }
            float uv = __shfl_xor_sync(FULL, vmin, o);
            int   ui = __shfl_xor_sync(FULL, imin, o);
            if (uv < vmin || (uv == vmin && ui < imin)) { vmin = uv; imin = ui; }
        }
        if (lane == 0) {
            size_t o = (size_t)m * NW + n;
            out[o] = vmax + vmin + bias[n];
            if (widx) {
                out[MN + o]     = (float)imax;
                out[2 * MN + o] = (float)imin;
            }
        }
    }
}

// ---------------------------------------------------------------------------
// fallback exhaustive kernel (unexpected shapes only)
// ---------------------------------------------------------------------------
#define BM 128
#define BN 64
#define BK 16
#define TM 8
#define TN 4
#define THREADS 256

template <bool WIDX>
__global__ __launch_bounds__(THREADS)
void mam_kernel(const float* __restrict__ A, const float* __restrict__ W,
                const float* __restrict__ bias, float* __restrict__ out,
                int M, int N, int K) {
    __shared__ float As[BK][BM + 4];
    __shared__ float Ws[BK][BN + 4];
    const int tid = threadIdx.x;
    const int tx = tid & 15, ty = tid >> 4;
    const int m0 = blockIdx.y * BM, n0 = blockIdx.x * BN;
    float vmax[TM][TN], vmin[TM][TN];
    int   imax[TM][TN], imin[TM][TN];
#pragma unroll
    for (int i = 0; i < TM; i++)
#pragma unroll
        for (int j = 0; j < TN; j++) {
            vmax[i][j] = -CUDART_INF_F; vmin[i][j] = CUDART_INF_F;
            if (WIDX) { imax[i][j] = 0; imin[i][j] = 0; }
        }
    const float* Ablk = A + (size_t)m0 * K;
    const float* Wblk = W + (size_t)n0 * K;
    for (int k0 = 0; k0 < K; k0 += BK) {
#pragma unroll
        for (int r = 0; r < (BM * BK) / THREADS; r++) {
            int idx = tid + r * THREADS;
            As[idx & 15][idx >> 4] = Ablk[(size_t)(idx >> 4) * K + (k0 + (idx & 15))];
        }
#pragma unroll
        for (int r = 0; r < (BN * BK) / THREADS; r++) {
            int idx = tid + r * THREADS;
            Ws[idx & 15][idx >> 4] = Wblk[(size_t)(idx >> 4) * K + (k0 + (idx & 15))];
        }
        __syncthreads();
#pragma unroll 4
        for (int kk = 0; kk < BK; kk++) {
            float a[TM], w[TN];
#pragma unroll
            for (int i = 0; i < TM; i++) a[i] = As[kk][ty * TM + i];
#pragma unroll
            for (int j = 0; j < TN; j++) w[j] = Ws[kk][tx * TN + j];
            const int kg = k0 + kk;
#pragma unroll
            for (int i = 0; i < TM; i++)
#pragma unroll
                for (int j = 0; j < TN; j++) {
                    float p = a[i] * w[j];
                    bool gm = p > vmax[i][j];
                    vmax[i][j] = gm ? p : vmax[i][j];
                    if (WIDX) imax[i][j] = gm ? kg : imax[i][j];
                    bool gn = p < vmin[i][j];
                    vmin[i][j] = gn ? p : vmin[i][j];
                    if (WIDX) imin[i][j] = gn ? kg : imin[i][j];
                }
        }
        __syncthreads();
    }
    const size_t MN = (size_t)M * N;
#pragma unroll
    for (int i = 0; i < TM; i++) {
        int m = m0 + ty * TM + i;
        size_t row = (size_t)m * N + n0 + tx * TN;
#pragma unroll
        for (int j = 0; j < TN; j++) {
            out[row + j] = vmax[i][j] + vmin[i][j] + bias[n0 + tx * TN + j];
            if (WIDX) {
                out[MN + row + j] = (float)imax[i][j];
                out[2 * MN + row + j] = (float)imin[i][j];
            }
        }
    }
}

// ---------------------------------------------------------------------------
extern "C" void kernel_launch(void* const* d_in, const int* in_sizes, int n_in,
                              void* d_out, int out_size) {
    const float* x = (const float*)d_in[0];
    const float* w = (const float*)d_in[1];
    const float* b = (const float*)d_in[2];
    float* out = (float*)d_out;

    const int N = in_sizes[2];
    const int K = in_sizes[1] / N;
    const int M = in_sizes[0] / K;
    const long long MN = (long long)M * (long long)N;
    const int widx = ((long long)out_size >= 3 * MN) ? 1 : 0;

    if (K == 1024 && N == 1024 && M <= MAXM && (M % 32) == 0) {
        float* At; cudaGetSymbolAddress((void**)&At, g_At);
        float* Wt; cudaGetSymbolAddress((void**)&Wt, g_Wt);

        {   // merged transpose: A row-tiles then W row-tiles
            dim3 blk(32, 8);
            dim3 g(M / 32 + 1024 / 32, 32);
            transpose2_kernel<<<g, blk>>>(x, w, At, Wt, M);
        }
        // merged topk (also zeroes worklist counter)
        topk_kernel<<<(M + N) / 8, 256>>>(x, w, M, N);

        dim3 grid(N / 32, M / 32);
        if (widx) mam_cand_kernel<1><<<grid, 1024>>>(At, Wt, b, out, M);
        else      mam_cand_kernel<0><<<grid, 1024>>>(At, Wt, b, out, M);

        cleanup_kernel<<<1184, 256>>>(x, w, b, out, M, widx);
    } else {
        dim3 grid(N / BN, M / BM);
        if (widx) mam_kernel<true><<<grid, THREADS>>>(x, w, b, out, M, N, K);
        else      mam_kernel<false><<<grid, THREADS>>>(x, w, b, out, M, N, K);
    }
}